// round 16
// baseline (speedup 1.0000x reference)
#include <cuda_runtime.h>

// DSQG attention, J=12 fixed causal offsets.
// q,k,v [B=2,H=16,N=4096,HD=64] f32; pb [12,16]; se [12,64];
// phase_base/gain [8,16,2]; y_pre/z_pre [B,H,N,2]. Output [B,H,N,64] f32.
//
// R16: R15 + Blackwell 256-bit loads. Lane lg owns dims [8lg..8lg+7];
//      each k/v fetch is ONE ld.global.nc.v8.f32 (LDG.256) instead of two
//      LDG.128s. Same bytes/wavefronts, half the load instructions and
//      LSU dispatch slots. Rest identical to R15 (block-uniform FULL split,
//      qse hoist, exp2 softmax, accumulate-then-correct epilogue, stcs).

#define NOFF 12

__device__ __forceinline__ void ldg256(const float* p, float4& a, float4& b) {
    asm("ld.global.nc.v8.f32 {%0,%1,%2,%3,%4,%5,%6,%7}, [%8];"
        : "=f"(a.x), "=f"(a.y), "=f"(a.z), "=f"(a.w),
          "=f"(b.x), "=f"(b.y), "=f"(b.z), "=f"(b.w)
        : "l"(p));
}

template <bool FULL>
__device__ __forceinline__ void dsqg_body(
    const float* __restrict__ q, const float* __restrict__ k,
    const float* __restrict__ v, const float* __restrict__ z_pre,
    const float* __restrict__ y_pre, const float* se_s,
    const float* pbl_s, const float* pbase_s, const float* pgain_s,
    float* __restrict__ out, int row, int n, int lg)
{
    constexpr int OFF[NOFF] = {1, 2, 4, 8, 16, 64, 96, 192, 384, 512, 768, 1024};
    const float LOG2E = 1.44269504f;
    const float scl = 0.125f * LOG2E;

    // lane lg owns dims [8lg .. 8lg+7]
    float4 q1, q2;
    ldg256(q + row * 64 + lg * 8, q1, q2);

    // per-lane partials of q . se_i (smem: two LDS.128s, prologue only)
    float qse_p[NOFF];
#pragma unroll
    for (int i = 0; i < NOFF; i++) {
        const float4 s1 = *(const float4*)(se_s + i * 64 + lg * 8);
        const float4 s2 = *(const float4*)(se_s + i * 64 + lg * 8 + 4);
        qse_p[i] = q1.x * s1.x + q1.y * s1.y + q1.z * s1.z + q1.w * s1.w
                 + q2.x * s2.x + q2.y * s2.y + q2.z * s2.z + q2.w * s2.w;
    }

    float sum = 0.f;
    float w = 0.f;   // e[lg+4] for the rotation epilogue
    float4 o1 = make_float4(0.f, 0.f, 0.f, 0.f);
    float4 o2 = make_float4(0.f, 0.f, 0.f, 0.f);

#pragma unroll
    for (int i = 0; i < NOFF; i++) {
        const int d = OFF[i];
        float4 k1, k2, v1, v2;
        if (FULL) {
            ldg256(k + (row - d) * 64 + lg * 8, k1, k2);
            ldg256(v + (row - d) * 64 + lg * 8, v1, v2);
        } else {
            k1 = make_float4(0.f, 0.f, 0.f, 0.f);
            k2 = make_float4(0.f, 0.f, 0.f, 0.f);
            v1 = make_float4(0.f, 0.f, 0.f, 0.f);
            v2 = make_float4(0.f, 0.f, 0.f, 0.f);
            if (n >= d) {
                ldg256(k + (row - d) * 64 + lg * 8, k1, k2);
                ldg256(v + (row - d) * 64 + lg * 8, v1, v2);
            }
        }

        float p = qse_p[i]
                + q1.x * k1.x + q1.y * k1.y + q1.z * k1.z + q1.w * k1.w
                + q2.x * k2.x + q2.y * k2.y + q2.z * k2.z + q2.w * k2.w;
        p += __shfl_xor_sync(0xffffffffu, p, 4);
        p += __shfl_xor_sync(0xffffffffu, p, 2);
        p += __shfl_xor_sync(0xffffffffu, p, 1);

        float ei;
        if (FULL) ei = exp2f(p * scl + pbl_s[i]);
        else      ei = (n >= d) ? exp2f(p * scl + pbl_s[i]) : 0.f;
        sum += ei;

        if (i >= 4) {
            if (lg == i - 4) w = ei;   // SEL, not a branch
        }
        // unconditional accumulate; epilogue subtracts the unrotated part
        o1.x += ei * v1.x; o1.y += ei * v1.y;
        o1.z += ei * v1.z; o1.w += ei * v1.w;
        o2.x += ei * v2.x; o2.y += ei * v2.y;
        o2.z += ei * v2.z; o2.w += ei * v2.w;
    }

    // ---- rotation epilogue: lane j handles offset j+4; contribution is
    //      w*(R(vv) - vv), cancelling the loop's unrotated w*vv exactly.
    //      Dims 0..3 are lane 0's first float4 (o1). ----
    {
        const int j = lg;
        int d;
        if (j < 4) d = (j < 2) ? ((j == 0) ? 16 : 64) : ((j == 2) ? 96 : 192);
        else       d = (j < 6) ? ((j == 4) ? 384 : 512) : ((j == 6) ? 768 : 1024);

        float4 vv;
        float2 zz;
        if (FULL) {
            vv = *(const float4*)(v + (row - d) * 64);
            zz = *(const float2*)(z_pre + (row - d) * 2);
        } else {
            vv = make_float4(0.f, 0.f, 0.f, 0.f);
            zz = make_float2(0.f, 0.f);
            if (n >= d) {
                vv = *(const float4*)(v + (row - d) * 64);
                zz = *(const float2*)(z_pre + (row - d) * 2);
            }
        }
        const float2 yv = *(const float2*)(y_pre + row * 2);
        const float t0 = pbase_s[j * 2 + 0] + pgain_s[j * 2 + 0] * yv.x * zz.x;
        const float t1 = pbase_s[j * 2 + 1] + pgain_s[j * 2 + 1] * yv.y * zz.y;
        float s0, c0, s1, c1;
        __sincosf(t0, &s0, &c0);
        __sincosf(t1, &s1, &c1);
        const float ac0 = w * c0, as0 = w * s0;
        const float ac1 = w * c1, as1 = w * s1;
        float r0 = ac0 * vv.x - as0 * vv.y - w * vv.x;
        float r1 = as0 * vv.x + ac0 * vv.y - w * vv.y;
        float r2 = ac1 * vv.z - as1 * vv.w - w * vv.z;
        float r3 = as1 * vv.z + ac1 * vv.w - w * vv.w;
#pragma unroll
        for (int m = 4; m >= 1; m >>= 1) {
            r0 += __shfl_xor_sync(0xffffffffu, r0, m);
            r1 += __shfl_xor_sync(0xffffffffu, r1, m);
            r2 += __shfl_xor_sync(0xffffffffu, r2, m);
            r3 += __shfl_xor_sync(0xffffffffu, r3, m);
        }
        if (lg == 0) {
            o1.x += r0; o1.y += r1; o1.z += r2; o1.w += r3;
        }
    }

    float inv;
    if (FULL) inv = __fdividef(1.f, sum);
    else      inv = (sum > 0.f) ? __fdividef(1.f, sum) : 0.f;
    o1.x *= inv; o1.y *= inv; o1.z *= inv; o1.w *= inv;
    o2.x *= inv; o2.y *= inv; o2.z *= inv; o2.w *= inv;

    __stcs((float4*)(out + row * 64 + lg * 8), o1);
    __stcs((float4*)(out + row * 64 + lg * 8 + 4), o2);
}

__global__ void __launch_bounds__(256, 4)
dsqg_kernel(const float* __restrict__ q,
            const float* __restrict__ k,
            const float* __restrict__ v,
            const float* __restrict__ pb,          // [12, H]
            const float* __restrict__ se,          // [12, 64]
            const float* __restrict__ phase_base,  // [8, H, 2]
            const float* __restrict__ phase_gain,  // [8, H, 2]
            const float* __restrict__ y_pre,       // [B,H,N,2]
            const float* __restrict__ z_pre,       // [B,H,N,2]
            float* __restrict__ out)
{
    constexpr int H = 16;
    constexpr int N = 4096;
    const float LOG2E = 1.44269504f;

    __shared__ __align__(16) float se_s[NOFF * 64];
    __shared__ float pbl_s[NOFF];
    __shared__ float pbase_s[16];
    __shared__ float pgain_s[16];

    const int tid  = threadIdx.x;
    const int warp = tid >> 5;
    const int lane = tid & 31;
    const int lg   = lane & 7;

    const int rbase = blockIdx.x * 32;
    const int h = (rbase >> 12) & (H - 1);

    for (int i = tid; i < NOFF * 64; i += 256) se_s[i] = se[i];
    if (tid < NOFF) pbl_s[tid] = pb[tid * H + h] * LOG2E;
    if (tid < 16) {
        const int pi = tid >> 1, p = tid & 1;
        pbase_s[tid] = phase_base[pi * (H * 2) + h * 2 + p];
        pgain_s[tid] = phase_gain[pi * (H * 2) + h * 2 + p];
    }
    __syncthreads();

    const int row = rbase + warp * 4 + (lane >> 3);
    const int n = row & (N - 1);

    // block-uniform: all 32 rows fully valid iff (rbase % N) >= 1024
    if ((rbase & (N - 1)) >= 1024) {
        dsqg_body<true>(q, k, v, z_pre, y_pre, se_s, pbl_s, pbase_s, pgain_s,
                        out, row, n, lg);
    } else {
        dsqg_body<false>(q, k, v, z_pre, y_pre, se_s, pbl_s, pbase_s, pgain_s,
                         out, row, n, lg);
    }
}

extern "C" void kernel_launch(void* const* d_in, const int* in_sizes, int n_in,
                              void* d_out, int out_size)
{
    const float* q          = (const float*)d_in[0];
    const float* k          = (const float*)d_in[1];
    const float* v          = (const float*)d_in[2];
    const float* pb         = (const float*)d_in[3];
    const float* se         = (const float*)d_in[4];
    const float* phase_base = (const float*)d_in[5];
    const float* phase_gain = (const float*)d_in[6];
    const float* y_pre      = (const float*)d_in[7];
    const float* z_pre      = (const float*)d_in[8];
    float* out = (float*)d_out;

    const int blocks = 131072 / 32;
    dsqg_kernel<<<blocks, 256>>>(q, k, v, pb, se, phase_base, phase_gain,
                                 y_pre, z_pre, out);
}

// round 17
// speedup vs baseline: 1.1600x; 1.1600x over previous
#include <cuda_runtime.h>

// DSQG attention, J=12 fixed causal offsets.
// q,k,v [B=2,H=16,N=4096,HD=64] f32; pb [12,16]; se [12,64];
// phase_base/gain [8,16,2]; y_pre/z_pre [B,H,N,2]. Output [B,H,N,64] f32.
//
// R17: R15 + depth-1 software pipelining of the FULL path's k/v loads:
//      iteration i issues iteration i+1's four LDG.128s before computing
//      i's score, doubling loads-in-flight per warp. ~80 regs / 3 CTAs-SM.
//      Boundary path (25% of blocks) stays the unpipelined R15 body.

#define NOFF 12

__device__ __forceinline__ void dsqg_full(
    const float* __restrict__ q, const float* __restrict__ k,
    const float* __restrict__ v, const float* __restrict__ z_pre,
    const float* __restrict__ y_pre, const float* se_s,
    const float* pbl_s, const float* pbase_s, const float* pgain_s,
    float* __restrict__ out, int row, int lg)
{
    constexpr int OFF[NOFF] = {1, 2, 4, 8, 16, 64, 96, 192, 384, 512, 768, 1024};
    const float LOG2E = 1.44269504f;
    const float scl = 0.125f * LOG2E;

    const float4 q1 = *(const float4*)(q + row * 64 + lg * 4);
    const float4 q2 = *(const float4*)(q + row * 64 + 32 + lg * 4);

    float qse_p[NOFF];
#pragma unroll
    for (int i = 0; i < NOFF; i++) {
        const float4 s1 = *(const float4*)(se_s + i * 64 + lg * 4);
        const float4 s2 = *(const float4*)(se_s + i * 64 + 32 + lg * 4);
        qse_p[i] = q1.x * s1.x + q1.y * s1.y + q1.z * s1.z + q1.w * s1.w
                 + q2.x * s2.x + q2.y * s2.y + q2.z * s2.z + q2.w * s2.w;
    }

    float sum = 0.f;
    float w = 0.f;
    float4 o1 = make_float4(0.f, 0.f, 0.f, 0.f);
    float4 o2 = make_float4(0.f, 0.f, 0.f, 0.f);

    // prefetch iteration 0
    const float* kb0 = k + (row - OFF[0]) * 64;
    const float* vb0 = v + (row - OFF[0]) * 64;
    float4 k1n = *(const float4*)(kb0 + lg * 4);
    float4 k2n = *(const float4*)(kb0 + 32 + lg * 4);
    float4 v1n = *(const float4*)(vb0 + lg * 4);
    float4 v2n = *(const float4*)(vb0 + 32 + lg * 4);

#pragma unroll
    for (int i = 0; i < NOFF; i++) {
        const float4 k1 = k1n, k2 = k2n, v1 = v1n, v2 = v2n;

        if (i + 1 < NOFF) {   // issue next iteration's loads NOW
            const float* kb = k + (row - OFF[i + 1]) * 64;
            const float* vb = v + (row - OFF[i + 1]) * 64;
            k1n = *(const float4*)(kb + lg * 4);
            k2n = *(const float4*)(kb + 32 + lg * 4);
            v1n = *(const float4*)(vb + lg * 4);
            v2n = *(const float4*)(vb + 32 + lg * 4);
        }

        float p = qse_p[i]
                + q1.x * k1.x + q1.y * k1.y + q1.z * k1.z + q1.w * k1.w
                + q2.x * k2.x + q2.y * k2.y + q2.z * k2.z + q2.w * k2.w;
        p += __shfl_xor_sync(0xffffffffu, p, 4);
        p += __shfl_xor_sync(0xffffffffu, p, 2);
        p += __shfl_xor_sync(0xffffffffu, p, 1);

        const float ei = exp2f(p * scl + pbl_s[i]);
        sum += ei;

        if (i >= 4) {
            if (lg == i - 4) w = ei;
        }
        o1.x += ei * v1.x; o1.y += ei * v1.y;
        o1.z += ei * v1.z; o1.w += ei * v1.w;
        o2.x += ei * v2.x; o2.y += ei * v2.y;
        o2.z += ei * v2.z; o2.w += ei * v2.w;
    }

    // rotation epilogue: lane j handles offset j+4; adds w*(R(vv)-vv)
    {
        const int j = lg;
        int d;
        if (j < 4) d = (j < 2) ? ((j == 0) ? 16 : 64) : ((j == 2) ? 96 : 192);
        else       d = (j < 6) ? ((j == 4) ? 384 : 512) : ((j == 6) ? 768 : 1024);

        const float4 vv = *(const float4*)(v + (row - d) * 64);
        const float2 zz = *(const float2*)(z_pre + (row - d) * 2);
        const float2 yv = *(const float2*)(y_pre + row * 2);
        const float t0 = pbase_s[j * 2 + 0] + pgain_s[j * 2 + 0] * yv.x * zz.x;
        const float t1 = pbase_s[j * 2 + 1] + pgain_s[j * 2 + 1] * yv.y * zz.y;
        float s0, c0, s1, c1;
        __sincosf(t0, &s0, &c0);
        __sincosf(t1, &s1, &c1);
        const float ac0 = w * c0, as0 = w * s0;
        const float ac1 = w * c1, as1 = w * s1;
        float r0 = ac0 * vv.x - as0 * vv.y - w * vv.x;
        float r1 = as0 * vv.x + ac0 * vv.y - w * vv.y;
        float r2 = ac1 * vv.z - as1 * vv.w - w * vv.z;
        float r3 = as1 * vv.z + ac1 * vv.w - w * vv.w;
#pragma unroll
        for (int m = 4; m >= 1; m >>= 1) {
            r0 += __shfl_xor_sync(0xffffffffu, r0, m);
            r1 += __shfl_xor_sync(0xffffffffu, r1, m);
            r2 += __shfl_xor_sync(0xffffffffu, r2, m);
            r3 += __shfl_xor_sync(0xffffffffu, r3, m);
        }
        if (lg == 0) {
            o1.x += r0; o1.y += r1; o1.z += r2; o1.w += r3;
        }
    }

    const float inv = __fdividef(1.f, sum);
    o1.x *= inv; o1.y *= inv; o1.z *= inv; o1.w *= inv;
    o2.x *= inv; o2.y *= inv; o2.z *= inv; o2.w *= inv;

    __stcs((float4*)(out + row * 64 + lg * 4), o1);
    __stcs((float4*)(out + row * 64 + 32 + lg * 4), o2);
}

__device__ __forceinline__ void dsqg_boundary(
    const float* __restrict__ q, const float* __restrict__ k,
    const float* __restrict__ v, const float* __restrict__ z_pre,
    const float* __restrict__ y_pre, const float* se_s,
    const float* pbl_s, const float* pbase_s, const float* pgain_s,
    float* __restrict__ out, int row, int n, int lg)
{
    constexpr int OFF[NOFF] = {1, 2, 4, 8, 16, 64, 96, 192, 384, 512, 768, 1024};
    const float LOG2E = 1.44269504f;
    const float scl = 0.125f * LOG2E;

    const float4 q1 = *(const float4*)(q + row * 64 + lg * 4);
    const float4 q2 = *(const float4*)(q + row * 64 + 32 + lg * 4);

    float qse_p[NOFF];
#pragma unroll
    for (int i = 0; i < NOFF; i++) {
        const float4 s1 = *(const float4*)(se_s + i * 64 + lg * 4);
        const float4 s2 = *(const float4*)(se_s + i * 64 + 32 + lg * 4);
        qse_p[i] = q1.x * s1.x + q1.y * s1.y + q1.z * s1.z + q1.w * s1.w
                 + q2.x * s2.x + q2.y * s2.y + q2.z * s2.z + q2.w * s2.w;
    }

    float sum = 0.f;
    float w = 0.f;
    float4 o1 = make_float4(0.f, 0.f, 0.f, 0.f);
    float4 o2 = make_float4(0.f, 0.f, 0.f, 0.f);

#pragma unroll
    for (int i = 0; i < NOFF; i++) {
        const int d = OFF[i];
        float4 k1 = make_float4(0.f, 0.f, 0.f, 0.f);
        float4 k2 = make_float4(0.f, 0.f, 0.f, 0.f);
        float4 v1 = make_float4(0.f, 0.f, 0.f, 0.f);
        float4 v2 = make_float4(0.f, 0.f, 0.f, 0.f);
        if (n >= d) {
            const float* kb = k + (row - d) * 64;
            const float* vb = v + (row - d) * 64;
            k1 = *(const float4*)(kb + lg * 4);
            k2 = *(const float4*)(kb + 32 + lg * 4);
            v1 = *(const float4*)(vb + lg * 4);
            v2 = *(const float4*)(vb + 32 + lg * 4);
        }

        float p = qse_p[i]
                + q1.x * k1.x + q1.y * k1.y + q1.z * k1.z + q1.w * k1.w
                + q2.x * k2.x + q2.y * k2.y + q2.z * k2.z + q2.w * k2.w;
        p += __shfl_xor_sync(0xffffffffu, p, 4);
        p += __shfl_xor_sync(0xffffffffu, p, 2);
        p += __shfl_xor_sync(0xffffffffu, p, 1);

        const float ei = (n >= d) ? exp2f(p * scl + pbl_s[i]) : 0.f;
        sum += ei;

        if (i >= 4) {
            if (lg == i - 4) w = ei;
        }
        o1.x += ei * v1.x; o1.y += ei * v1.y;
        o1.z += ei * v1.z; o1.w += ei * v1.w;
        o2.x += ei * v2.x; o2.y += ei * v2.y;
        o2.z += ei * v2.z; o2.w += ei * v2.w;
    }

    {
        const int j = lg;
        int d;
        if (j < 4) d = (j < 2) ? ((j == 0) ? 16 : 64) : ((j == 2) ? 96 : 192);
        else       d = (j < 6) ? ((j == 4) ? 384 : 512) : ((j == 6) ? 768 : 1024);

        float4 vv = make_float4(0.f, 0.f, 0.f, 0.f);
        float2 zz = make_float2(0.f, 0.f);
        if (n >= d) {
            vv = *(const float4*)(v + (row - d) * 64);
            zz = *(const float2*)(z_pre + (row - d) * 2);
        }
        const float2 yv = *(const float2*)(y_pre + row * 2);
        const float t0 = pbase_s[j * 2 + 0] + pgain_s[j * 2 + 0] * yv.x * zz.x;
        const float t1 = pbase_s[j * 2 + 1] + pgain_s[j * 2 + 1] * yv.y * zz.y;
        float s0, c0, s1, c1;
        __sincosf(t0, &s0, &c0);
        __sincosf(t1, &s1, &c1);
        const float ac0 = w * c0, as0 = w * s0;
        const float ac1 = w * c1, as1 = w * s1;
        float r0 = ac0 * vv.x - as0 * vv.y - w * vv.x;
        float r1 = as0 * vv.x + ac0 * vv.y - w * vv.y;
        float r2 = ac1 * vv.z - as1 * vv.w - w * vv.z;
        float r3 = as1 * vv.z + ac1 * vv.w - w * vv.w;
#pragma unroll
        for (int m = 4; m >= 1; m >>= 1) {
            r0 += __shfl_xor_sync(0xffffffffu, r0, m);
            r1 += __shfl_xor_sync(0xffffffffu, r1, m);
            r2 += __shfl_xor_sync(0xffffffffu, r2, m);
            r3 += __shfl_xor_sync(0xffffffffu, r3, m);
        }
        if (lg == 0) {
            o1.x += r0; o1.y += r1; o1.z += r2; o1.w += r3;
        }
    }

    const float inv = (sum > 0.f) ? __fdividef(1.f, sum) : 0.f;
    o1.x *= inv; o1.y *= inv; o1.z *= inv; o1.w *= inv;
    o2.x *= inv; o2.y *= inv; o2.z *= inv; o2.w *= inv;

    __stcs((float4*)(out + row * 64 + lg * 4), o1);
    __stcs((float4*)(out + row * 64 + 32 + lg * 4), o2);
}

__global__ void __launch_bounds__(256, 3)
dsqg_kernel(const float* __restrict__ q,
            const float* __restrict__ k,
            const float* __restrict__ v,
            const float* __restrict__ pb,          // [12, H]
            const float* __restrict__ se,          // [12, 64]
            const float* __restrict__ phase_base,  // [8, H, 2]
            const float* __restrict__ phase_gain,  // [8, H, 2]
            const float* __restrict__ y_pre,       // [B,H,N,2]
            const float* __restrict__ z_pre,       // [B,H,N,2]
            float* __restrict__ out)
{
    constexpr int H = 16;
    constexpr int N = 4096;
    const float LOG2E = 1.44269504f;

    __shared__ __align__(16) float se_s[NOFF * 64];
    __shared__ float pbl_s[NOFF];
    __shared__ float pbase_s[16];
    __shared__ float pgain_s[16];

    const int tid  = threadIdx.x;
    const int warp = tid >> 5;
    const int lane = tid & 31;
    const int lg   = lane & 7;

    const int rbase = blockIdx.x * 32;
    const int h = (rbase >> 12) & (H - 1);

    for (int i = tid; i < NOFF * 64; i += 256) se_s[i] = se[i];
    if (tid < NOFF) pbl_s[tid] = pb[tid * H + h] * LOG2E;
    if (tid < 16) {
        const int pi = tid >> 1, p = tid & 1;
        pbase_s[tid] = phase_base[pi * (H * 2) + h * 2 + p];
        pgain_s[tid] = phase_gain[pi * (H * 2) + h * 2 + p];
    }
    __syncthreads();

    const int row = rbase + warp * 4 + (lane >> 3);
    const int n = row & (N - 1);

    if ((rbase & (N - 1)) >= 1024) {
        dsqg_full(q, k, v, z_pre, y_pre, se_s, pbl_s, pbase_s, pgain_s,
                  out, row, lg);
    } else {
        dsqg_boundary(q, k, v, z_pre, y_pre, se_s, pbl_s, pbase_s, pgain_s,
                      out, row, n, lg);
    }
}

extern "C" void kernel_launch(void* const* d_in, const int* in_sizes, int n_in,
                              void* d_out, int out_size)
{
    const float* q          = (const float*)d_in[0];
    const float* k          = (const float*)d_in[1];
    const float* v          = (const float*)d_in[2];
    const float* pb         = (const float*)d_in[3];
    const float* se         = (const float*)d_in[4];
    const float* phase_base = (const float*)d_in[5];
    const float* phase_gain = (const float*)d_in[6];
    const float* y_pre      = (const float*)d_in[7];
    const float* z_pre      = (const float*)d_in[8];
    float* out = (float*)d_out;

    const int blocks = 131072 / 32;
    dsqg_kernel<<<blocks, 256>>>(q, k, v, pb, se, phase_base, phase_gain,
                                 y_pre, z_pre, out);
}